// round 9
// baseline (speedup 1.0000x reference)
#include <cuda_runtime.h>
#include <cuda_fp16.h>
#include <cstdint>

// ---------------------------------------------------------------------------
// LigEdgeBuilder: edge_attr = lig_ea + emb(d),  d = |pos[dst]-pos[src]|
// KEY INSIGHT: emb = relu(gauss(d)@W1+b1)@W2+b2 is a smooth function of the
// SCALAR d alone -> precompute a 1-D table emb(d) (fp32 math, fp16 storage),
// then the main kernel is pure streaming: gather d, lerp table, add, store.
//   table: 4420 rows (d step 1/128, covers d in [0,34.5]; beyond: emb==b2),
//          64 cols fp16 = 553 KB, L2-resident.
//   interp err ~2e-6, fp16 quant ~7e-5 -> rel_err ~1e-4 (< current 3.9e-4)
// ---------------------------------------------------------------------------

#define TROWS  4420
#define INVH   128.0f
#define THREADS 256
#define WARPS_PB (THREADS / 32)

__device__ __half g_table[TROWS * 64];

// ---- table builder: one block per d-row, 64 threads (one per column) ----
__global__ void build_table(const float* __restrict__ W1,
                            const float* __restrict__ b1,
                            const float* __restrict__ W2,
                            const float* __restrict__ b2)
{
    __shared__ float gg[50];
    __shared__ float hh[64];
    const int row = blockIdx.x;
    const int j   = threadIdx.x;
    const float d = (float)row * (1.0f / INVH);
    const float step  = 30.0f / 49.0f;
    const float coeff = -0.5f / (step * step);

    if (j < 50) {
        float t = d - (float)j * step;
        gg[j] = expf(coeff * t * t);
    }
    __syncthreads();

    float acc = b1[j];
#pragma unroll 10
    for (int r = 0; r < 50; r++) acc = fmaf(gg[r], W1[r * 64 + j], acc);
    hh[j] = fmaxf(acc, 0.0f);
    __syncthreads();

    float acc2 = b2[j];
#pragma unroll 16
    for (int k = 0; k < 64; k++) acc2 = fmaf(hh[k], W2[k * 64 + j], acc2);
    g_table[row * 64 + j] = __float2half(acc2);
}

// ---- main kernel: 16 edges per warp, 2 lanes per edge (32 cols each) ----
__global__ void __launch_bounds__(THREADS, 3)
lig_edge_kernel(const float* __restrict__ pos,
                const float* __restrict__ lig_ea,
                const void*  __restrict__ ei_raw,
                float* __restrict__ outAttr,
                int E, int numTiles)
{
    const int tid  = threadIdx.x;
    const int lane = tid & 31;
    const int warp = tid >> 5;

    const long long* ei64 = (const long long*)ei_raw;
    const int*       ei32 = (const int*)ei_raw;

    // ---- edge_index dtype detection (per warp, once) ----
    int idx64;
    {
        long long v = 0;
        if (lane < 16 && lane < E) v = ei64[lane];
        int ok = (v >= 0 && v < (1LL << 31));
        idx64 = __all_sync(0xffffffffu, ok) ? 1 : 0;
    }

    const int gwarp      = blockIdx.x * WARPS_PB + warp;
    const int totalWarps = gridDim.x * WARPS_PB;

    for (int tile = gwarp; tile < numTiles; tile += totalWarps) {
        const int e0 = tile * 16;

        // ---- distances: lanes 0..15 load src endpoint, 16..31 dst ----
        const int eL = e0 + (lane & 15);
        int nodeIdx = 0;
        if (eL < E) {
            int sel = (lane < 16) ? eL : (E + eL);
            nodeIdx = idx64 ? (int)ei64[sel] : ei32[sel];
        }
        const float* P = pos + (unsigned)nodeIdx * 3u;
        float x = P[0], y = P[1], z = P[2];
        float dx = __shfl_xor_sync(0xffffffffu, x, 16) - x;
        float dy = __shfl_xor_sync(0xffffffffu, y, 16) - y;
        float dz = __shfl_xor_sync(0xffffffffu, z, 16) - z;
        float dwarp = sqrtf(dx * dx + dy * dy + dz * dz);  // d of edge (lane&15)

        // ---- per-lane edge assignment: 2 lanes per edge ----
        const int el   = lane >> 1;    // local edge 0..15
        const int half = lane & 1;     // 32-column half
        const float de = __shfl_sync(0xffffffffu, dwarp, el);
        const int e    = e0 + el;
        const bool v   = (e < E);

        // ---- issue lig loads early (DRAM latency, independent of d) ----
        const float4* lp = (const float4*)(lig_ea + (unsigned)e * 64u + half * 32);
        float4 lg[8];
        if (v) {
#pragma unroll
            for (int i = 0; i < 8; i++) lg[i] = __ldcs(lp + i);
        }

        // ---- table rows (L2-resident) + interpolation factor ----
        float tt = fminf(de * INVH, (float)(TROWS - 2));
        int   i0 = (int)tt;
        float fr = tt - (float)i0;
        const uint4* t0p = (const uint4*)(g_table + (unsigned)i0 * 64u + half * 32);
        const uint4* t1p = t0p + 8;    // next d-row: +64 halves = 8 uint4
        uint4 t0[4], t1[4];
        if (v) {
#pragma unroll
            for (int i = 0; i < 4; i++) { t0[i] = __ldg(t0p + i); t1[i] = __ldg(t1p + i); }
        }

        // ---- lerp + add + streaming store ----
        if (v) {
            float4* outp = (float4*)(outAttr + (unsigned)e * 64u + half * 32);
#pragma unroll
            for (int i = 0; i < 4; i++) {
                const uint32_t* a = &t0[i].x;
                const uint32_t* b = &t1[i].x;
                float4 o0, o1;
                float* oo = &o0.x;
#pragma unroll
                for (int c = 0; c < 4; c++) {
                    float2 fa = __half22float2(*(const __half2*)&a[c]);
                    float2 fb = __half22float2(*(const __half2*)&b[c]);
                    oo[2 * c]     = fa.x + fr * (fb.x - fa.x);
                    oo[2 * c + 1] = fa.y + fr * (fb.y - fa.y);
                }
                // oo wrote o0.xyzw then o1.xyzw (contiguous on stack layout is
                // not guaranteed) -> do explicitly instead:
                // (rewritten below without the pointer trick)
                (void)o1;
                float2 f0 = __half22float2(*(const __half2*)&a[0]);
                float2 g0 = __half22float2(*(const __half2*)&b[0]);
                float2 f1 = __half22float2(*(const __half2*)&a[1]);
                float2 g1 = __half22float2(*(const __half2*)&b[1]);
                float2 f2 = __half22float2(*(const __half2*)&a[2]);
                float2 g2 = __half22float2(*(const __half2*)&b[2]);
                float2 f3 = __half22float2(*(const __half2*)&a[3]);
                float2 g3 = __half22float2(*(const __half2*)&b[3]);
                float4 r0, r1;
                r0.x = lg[2 * i].x     + f0.x + fr * (g0.x - f0.x);
                r0.y = lg[2 * i].y     + f0.y + fr * (g0.y - f0.y);
                r0.z = lg[2 * i].z     + f1.x + fr * (g1.x - f1.x);
                r0.w = lg[2 * i].w     + f1.y + fr * (g1.y - f1.y);
                r1.x = lg[2 * i + 1].x + f2.x + fr * (g2.x - f2.x);
                r1.y = lg[2 * i + 1].y + f2.y + fr * (g2.y - f2.y);
                r1.z = lg[2 * i + 1].z + f3.x + fr * (g3.x - f3.x);
                r1.w = lg[2 * i + 1].w + f3.y + fr * (g3.y - f3.y);
                __stcs(outp + 2 * i,     r0);
                __stcs(outp + 2 * i + 1, r1);
            }
        }
    }
}

// ---- optional edge_index output paths (self-detecting dtype) -------------
__device__ __forceinline__ int detect64(const void* ei, int E) {
    const long long* p = (const long long*)ei;
    int ok = 1;
    int n = E < 16 ? E : 16;
    for (int i = 0; i < n; i++) {
        long long v = p[i];
        if (v < 0 || v >= (1LL << 31)) { ok = 0; break; }
    }
    return ok;
}

__global__ void write_idx_float(const void* __restrict__ ei, float* __restrict__ out,
                                int n, int E) {
    int i = blockIdx.x * blockDim.x + threadIdx.x;
    if (i < n) {
        int is64 = detect64(ei, E);
        long long v = is64 ? ((const long long*)ei)[i] : (long long)((const int*)ei)[i];
        out[i] = (float)v;
    }
}

__global__ void write_idx_raw(const void* __restrict__ ei, long long* __restrict__ out,
                              int n, int E) {
    int i = blockIdx.x * blockDim.x + threadIdx.x;
    if (i < n) {
        int is64 = detect64(ei, E);
        long long v = is64 ? ((const long long*)ei)[i] : (long long)((const int*)ei)[i];
        out[i] = v;
    }
}

extern "C" void kernel_launch(void* const* d_in, const int* in_sizes, int n_in,
                              void* d_out, int out_size)
{
    const float* pos = nullptr;
    const float* lig = nullptr;
    const void*  ei  = nullptr;
    const float* W1  = nullptr;
    const float* b1  = nullptr;
    const float* W2  = nullptr;
    const float* b2  = nullptr;

    long long maxSz = -1; int ligIdx = -1;
    for (int i = 0; i < n_in; i++)
        if ((long long)in_sizes[i] > maxSz) { maxSz = in_sizes[i]; ligIdx = i; }
    lig = (const float*)d_in[ligIdx];
    const int E = (int)(maxSz / 64);

    for (int i = 0; i < n_in; i++) {
        long long sz = in_sizes[i];
        if (i == ligIdx) continue;
        if (sz == 50LL * 64)          W1 = (const float*)d_in[i];
        else if (sz == 64LL * 64)     W2 = (const float*)d_in[i];
        else if (sz == 64) {
            if (!b1) b1 = (const float*)d_in[i];
            else     b2 = (const float*)d_in[i];
        }
        else if (sz == 2LL * E || sz == 4LL * E) ei = d_in[i];
        else                        pos = (const float*)d_in[i];
    }

    float* out  = (float*)d_out;
    float* attr = out;
    const long long nAttr = (long long)E * 64;

    if ((long long)out_size == nAttr + 2LL * E) {
        int n = 2 * E;
        write_idx_float<<<(n + 255) / 256, 256>>>(ei, out, n, E);
        attr = out + 2LL * E;
    } else if ((long long)out_size == nAttr + 4LL * E) {
        int n = 2 * E;
        write_idx_raw<<<(n + 255) / 256, 256>>>(ei, (long long*)d_out, n, E);
        attr = out + 4LL * E;
    }

    // 1) build the emb(d) table (fp32 math, fp16 storage)
    build_table<<<TROWS, 64>>>(W1, b1, W2, b2);

    // 2) streaming main kernel
    const int numTiles = (E + 15) / 16;
    int grid = (numTiles + WARPS_PB - 1) / WARPS_PB;
    lig_edge_kernel<<<grid, THREADS>>>(pos, lig, ei, attr, E, numTiles);
}